// round 16
// baseline (speedup 1.0000x reference)
#include <cuda_runtime.h>
#include <cuda_fp16.h>
#include <cstdint>

#define NP   100000
#define NL   64
#define FP   128
#define FL   64
#define HD   128
#define ED   64
#define EC   1600000
#define EIS  100000
#define EREV 100000

// ---------------- scratch (device globals; no allocation allowed) ----------
__device__ float g_deg[NP];
__device__ float g_dis[NP];
__device__ uint32_t g_ys[NP * HD / 2];  // half2-packed dis*y (layer1: 64 words/row; layer2: 32)
__device__ float g_acc[NP * HD];        // layer-1 accumulator (128 cols)
__device__ float g_aggL1[NL * FP];
__device__ float g_aggL2[NL * HD];
__device__ float g_xlW1[NL * HD];
__device__ float g_xllin1[NL * HD];
__device__ float g_xl1[NL * HD];
__device__ float g_xlW2[NL * ED];
__device__ float g_xllin2[NL * ED];

// ---------------- helpers ---------------------------------------------------
__device__ __forceinline__ void red_add4(float* p, float a, float b, float c, float d) {
    asm volatile("red.global.add.v4.f32 [%0], {%1,%2,%3,%4};"
                 :: "l"(p), "f"(a), "f"(b), "f"(c), "f"(d) : "memory");
}
__device__ __forceinline__ void red_add1(float* p, float v) {
    asm volatile("red.global.add.f32 [%0], %1;" :: "l"(p), "f"(v) : "memory");
}

// pack two f32 into bf16x2 word: lo half = first arg
__device__ __forceinline__ uint32_t pack_bf2(float lo, float hi) {
    uint32_t u;
    asm("cvt.rn.bf16x2.f32 %0, %1, %2;" : "=r"(u) : "f"(hi), "f"(lo));
    return u;
}

__device__ __forceinline__ void mma_bf16(float* d, const uint32_t* a, uint32_t b0, uint32_t b1) {
    asm("mma.sync.aligned.m16n8k16.row.col.f32.bf16.bf16.f32 "
        "{%0,%1,%2,%3},{%4,%5,%6,%7},{%8,%9},{%0,%1,%2,%3};"
        : "+f"(d[0]), "+f"(d[1]), "+f"(d[2]), "+f"(d[3])
        : "r"(a[0]), "r"(a[1]), "r"(a[2]), "r"(a[3]), "r"(b0), "r"(b1));
}

__device__ __forceinline__ uint32_t pack_h2(float lo, float hi) {
    __half2 h = __float22half2_rn(make_float2(lo, hi));
    return *(uint32_t*)&h;
}

// ---------------- setup kernels ---------------------------------------------
__global__ void zero_all_kernel(float* deg, float* aggL1, float* aggL2) {
    int i = blockIdx.x * blockDim.x + threadIdx.x;
    if (i < NP) deg[i] = 0.f;
    else if (i < NP + NL * FP) aggL1[i - NP] = 0.f;
    else if (i < NP + NL * FP + NL * HD) aggL2[i - NP - NL * FP] = 0.f;
}

__global__ void deg_kernel(const int* __restrict__ dst, float* __restrict__ deg, int E4) {
    int i = blockIdx.x * blockDim.x + threadIdx.x;
    if (i < E4) {
        int4 v = ((const int4*)dst)[i];
        red_add1(&deg[v.x], 1.f);
        red_add1(&deg[v.y], 1.f);
        red_add1(&deg[v.z], 1.f);
        red_add1(&deg[v.w], 1.f);
    }
}

__global__ void dis_kernel(const float* __restrict__ deg, float* __restrict__ dis, int n) {
    int i = blockIdx.x * blockDim.x + threadIdx.x;
    if (i < n) dis[i] = rsqrtf(deg[i] + 1.f);
}

// ---------------- big dual GEMM via BF16 m16n8k16 mma.sync -------------------
// ys(half2) = OS * dis * (X @ Wa)
// acc(f32)  = OS * (X @ Wb + ba + bb + dis^2 * (X @ Wa))
// X/W converted to bf16x2 words in smem (packed along K). Full K=128 resident.
// CTA tile 64 x BN, 256 threads = 2(M) x 4(N) warps; warp tile 32 x BN/4.
template <int BN, bool PRE, bool HALF_OUT>
__global__ __launch_bounds__(256, 2)
void gemm_dual_bf16(const float* __restrict__ X,
                    const float* __restrict__ Wa,
                    const float* __restrict__ Wb,
                    const float* __restrict__ ba,
                    const float* __restrict__ bb,
                    const float* __restrict__ dis,
                    uint32_t* __restrict__ ys,
                    float* __restrict__ acc,
                    int M) {
    constexpr int K = 128;
    constexpr int KW = K / 2;         // 64 words along K
    constexpr int LDX = KW + 4;       // 68
    constexpr int LDW = BN + 8;       // 136 / 72
    constexpr int NAW = (BN / 4) / 8; // 4 (BN=128) / 2 (BN=64)
    constexpr float OS = HALF_OUT ? 0.5f : 1.0f;

    extern __shared__ uint32_t smu[];
    uint32_t* Xs = smu;                     // 64 * LDX
    uint32_t* Was = Xs + 64 * LDX;          // KW * LDW
    uint32_t* Wbs = Was + KW * LDW;         // KW * LDW
    float* bsum = (float*)(Wbs + KW * LDW); // BN

    const int tid = threadIdx.x;
    const int lane = tid & 31;
    const int wid = tid >> 5;
    const int wm = wid & 1;
    const int wn = wid >> 1;
    const int r = lane >> 2;
    const int c = lane & 3;
    const int row0 = blockIdx.x * 64;

    if (tid < BN) bsum[tid] = ba[tid] + bb[tid];

    // X tile: 64 rows x 128 cols -> bf16x2 words [row][kw]
    for (int idx = tid; idx < 64 * 32; idx += 256) {
        int rr = idx >> 5, c4 = idx & 31;
        float4 v = make_float4(0.f, 0.f, 0.f, 0.f);
        if (row0 + rr < M) {
            v = *(const float4*)(X + (size_t)(row0 + rr) * K + c4 * 4);
            if (PRE) {
                v.x = fmaxf(v.x * 0.5f, 0.f);
                v.y = fmaxf(v.y * 0.5f, 0.f);
                v.z = fmaxf(v.z * 0.5f, 0.f);
                v.w = fmaxf(v.w * 0.5f, 0.f);
            }
        }
        uint32_t* p = Xs + rr * LDX + c4 * 2;
        p[0] = pack_bf2(v.x, v.y);
        p[1] = pack_bf2(v.z, v.w);
    }
    // W tiles: words [kw][n] = pack(W[2kw][n], W[2kw+1][n])
    for (int idx = tid; idx < KW * (BN / 4); idx += 256) {
        int kw = idx / (BN / 4), cc = idx % (BN / 4);
        const float4 a0 = ((const float4*)(Wa + (size_t)(2 * kw) * BN))[cc];
        const float4 a1 = ((const float4*)(Wa + (size_t)(2 * kw + 1) * BN))[cc];
        const float4 b0 = ((const float4*)(Wb + (size_t)(2 * kw) * BN))[cc];
        const float4 b1 = ((const float4*)(Wb + (size_t)(2 * kw + 1) * BN))[cc];
        uint32_t* pa = Was + kw * LDW + cc * 4;
        uint32_t* pb = Wbs + kw * LDW + cc * 4;
        pa[0] = pack_bf2(a0.x, a1.x); pa[1] = pack_bf2(a0.y, a1.y);
        pa[2] = pack_bf2(a0.z, a1.z); pa[3] = pack_bf2(a0.w, a1.w);
        pb[0] = pack_bf2(b0.x, b1.x); pb[1] = pack_bf2(b0.y, b1.y);
        pb[2] = pack_bf2(b0.z, b1.z); pb[3] = pack_bf2(b0.w, b1.w);
    }
    __syncthreads();

    float accY[2][NAW][4];
    float accL[2][NAW][4];
#pragma unroll
    for (int i = 0; i < 2; i++)
#pragma unroll
        for (int j = 0; j < NAW; j++)
#pragma unroll
            for (int q = 0; q < 4; q++) { accY[i][j][q] = 0.f; accL[i][j][q] = 0.f; }

#pragma unroll
    for (int ks = 0; ks < 8; ks++) {
        int k0 = ks * 8;   // word offset
        uint32_t a[2][4];
#pragma unroll
        for (int i = 0; i < 2; i++) {
            int base = wm * 32 + i * 16;
            a[i][0] = Xs[(base + r) * LDX + k0 + c];
            a[i][1] = Xs[(base + r + 8) * LDX + k0 + c];
            a[i][2] = Xs[(base + r) * LDX + k0 + c + 4];
            a[i][3] = Xs[(base + r + 8) * LDX + k0 + c + 4];
        }
#pragma unroll
        for (int j = 0; j < NAW; j++) {
            int n = wn * (BN / 4) + j * 8 + r;
            uint32_t b0 = Was[(k0 + c) * LDW + n];
            uint32_t b1 = Was[(k0 + c + 4) * LDW + n];
            mma_bf16(accY[0][j], a[0], b0, b1);
            mma_bf16(accY[1][j], a[1], b0, b1);
            uint32_t b2 = Wbs[(k0 + c) * LDW + n];
            uint32_t b3 = Wbs[(k0 + c + 4) * LDW + n];
            mma_bf16(accL[0][j], a[0], b2, b3);
            mma_bf16(accL[1][j], a[1], b2, b3);
        }
    }

    // epilogue (same accumulator layout as m16n8k8)
#pragma unroll
    for (int i = 0; i < 2; i++) {
        int row_lo = row0 + wm * 32 + i * 16 + r;
        int row_hi = row_lo + 8;
        float dlo = (row_lo < M) ? dis[row_lo] : 0.f;
        float dhi = (row_hi < M) ? dis[row_hi] : 0.f;
#pragma unroll
        for (int j = 0; j < NAW; j++) {
            int cb = wn * (BN / 4) + j * 8 + c * 2;
            float bs0 = bsum[cb], bs1 = bsum[cb + 1];
            if (row_lo < M) {
                float y0 = accY[i][j][0], y1 = accY[i][j][1];
                float l0 = accL[i][j][0], l1 = accL[i][j][1];
                ys[(size_t)row_lo * (BN / 2) + (cb >> 1)] =
                    pack_h2(OS * dlo * y0, OS * dlo * y1);
                float2 ao = make_float2(OS * (l0 + bs0 + dlo * dlo * y0),
                                        OS * (l1 + bs1 + dlo * dlo * y1));
                *(float2*)(acc + (size_t)row_lo * BN + cb) = ao;
            }
            if (row_hi < M) {
                float y0 = accY[i][j][2], y1 = accY[i][j][3];
                float l0 = accL[i][j][2], l1 = accL[i][j][3];
                ys[(size_t)row_hi * (BN / 2) + (cb >> 1)] =
                    pack_h2(OS * dhi * y0, OS * dhi * y1);
                float2 ao = make_float2(OS * (l0 + bs0 + dhi * dhi * y0),
                                        OS * (l1 + bs1 + dhi * dhi * y1));
                *(float2*)(acc + (size_t)row_hi * BN + cb) = ao;
            }
        }
    }
}

// ---------------- fused edge kernel: cites + rev (+ label) ------------------
// block [0, BC)            : cites scatter, U=4 edges/group, LPE=F/8 lanes, uint4 loads
// block [BC, BC+512)       : rev scatter (tab in smem)
// block [BC+512, BC+1024)  : label scatter (WITH_LABEL only; F==128 path)
template <int F, bool WITH_LABEL, bool LPRE>
__global__ __launch_bounds__(256)
void fused_edge_kernel(const uint32_t* __restrict__ ys,
                       const float* __restrict__ dis,
                       const int* __restrict__ c_src,
                       const int* __restrict__ c_dst,
                       const float* __restrict__ tab,
                       const int* __restrict__ r_src,
                       const int* __restrict__ r_dst,
                       const float* __restrict__ LX,
                       const int* __restrict__ i_src,
                       const int* __restrict__ i_dst,
                       float* __restrict__ agg,
                       float* __restrict__ acc,
                       int BC) {
    __shared__ float s_tab[NL * F];
    const int b = blockIdx.x;
    const int tid = threadIdx.x;

    if (b < BC) {
        // ---- cites scatter ----
        constexpr int LPE = F / 8;   // 16 (F=128) or 8 (F=64)
        constexpr int U = 4;
        int gid = (b * 256 + tid) / LPE;
        int l = tid & (LPE - 1);
        int e0 = gid * U;
        if (e0 >= EC) return;
        int s[U], d[U];
        bool v[U];
#pragma unroll
        for (int u = 0; u < U; u++) {
            v[u] = (e0 + u) < EC;
            int e = v[u] ? (e0 + u) : e0;
            s[u] = __ldg(c_src + e);
            d[u] = __ldg(c_dst + e);
        }
        float dd[U];
#pragma unroll
        for (int u = 0; u < U; u++) dd[u] = __ldg(dis + d[u]);
        uint4 wv[U];
#pragma unroll
        for (int u = 0; u < U; u++)
            wv[u] = *(const uint4*)(ys + (size_t)s[u] * (F / 2) + l * 4);
#pragma unroll
        for (int u = 0; u < U; u++) {
            if (!v[u]) continue;
            float2 p0 = __half22float2(*(__half2*)&wv[u].x);
            float2 p1 = __half22float2(*(__half2*)&wv[u].y);
            float2 p2 = __half22float2(*(__half2*)&wv[u].z);
            float2 p3 = __half22float2(*(__half2*)&wv[u].w);
            float* p = acc + (size_t)d[u] * F + l * 8;
            red_add4(p, p0.x * dd[u], p0.y * dd[u], p1.x * dd[u], p1.y * dd[u]);
            red_add4(p + 4, p2.x * dd[u], p2.y * dd[u], p3.x * dd[u], p3.y * dd[u]);
        }
    } else if (b < BC + 512) {
        // ---- rev scatter: acc[dst] += tab[src] ----
        constexpr int LPE = F / 4;
        for (int i = tid; i < NL * F; i += 256) s_tab[i] = tab[i];
        __syncthreads();
        int b2 = b - BC;
        int ge = (b2 * 256 + tid) / LPE;
        int l = tid & (LPE - 1);
        int ne = (512 * 256) / LPE;
        for (int e = ge; e < EREV; e += ne) {
            int s = __ldg(r_src + e);
            int d = __ldg(r_dst + e);
            float4 v = *(const float4*)(s_tab + s * F + l * 4);
            float* p = acc + (size_t)d * F + l * 4;
            red_add4(p, v.x, v.y, v.z, v.w);
        }
    } else if (WITH_LABEL) {
        // ---- label scatter: agg[64,128] += LX[src] (rows of 128) ----
        for (int i = tid; i < NL * 128; i += 256) s_tab[i] = 0.f;
        __syncthreads();
        int b3 = b - BC - 512;
        int lane = tid & 31;
        int gw = b3 * 8 + (tid >> 5);
        int nw = 512 * 8;
        for (int e = gw; e < EIS; e += nw) {
            int s = __ldg(i_src + e);
            int d = __ldg(i_dst + e);
            float4 v = *(const float4*)(LX + (size_t)s * 128 + lane * 4);
            if (LPRE) {
                v.x = fmaxf(v.x * 0.5f, 0.f);
                v.y = fmaxf(v.y * 0.5f, 0.f);
                v.z = fmaxf(v.z * 0.5f, 0.f);
                v.w = fmaxf(v.w * 0.5f, 0.f);
            }
            float* p = s_tab + d * 128 + lane * 4;
            atomicAdd(p, v.x); atomicAdd(p + 1, v.y);
            atomicAdd(p + 2, v.z); atomicAdd(p + 3, v.w);
        }
        __syncthreads();
        for (int i = tid * 4; i < NL * 128; i += 256 * 4) {
            float4 v = *(float4*)(s_tab + i);
            red_add4(agg + i, v.x, v.y, v.z, v.w);
        }
    }
}

// ---------------- standalone label scatter (layer-2 'is' gather) ------------
template <bool PRE>
__global__ void scatter_label_kernel(const float* __restrict__ X,
                                     const int* __restrict__ src,
                                     const int* __restrict__ dst,
                                     float* __restrict__ out, int E) {
    __shared__ float s_acc[NL * 128];
    for (int i = threadIdx.x; i < NL * 128; i += blockDim.x) s_acc[i] = 0.f;
    __syncthreads();
    int warp_in = threadIdx.x >> 5;
    int lane = threadIdx.x & 31;
    int gw = blockIdx.x * (blockDim.x >> 5) + warp_in;
    int nw = gridDim.x * (blockDim.x >> 5);
    for (int e = gw; e < E; e += nw) {
        int s = __ldg(src + e);
        int d = __ldg(dst + e);
        float4 v = *(const float4*)(X + (size_t)s * 128 + lane * 4);
        if (PRE) {
            v.x = fmaxf(v.x * 0.5f, 0.f);
            v.y = fmaxf(v.y * 0.5f, 0.f);
            v.z = fmaxf(v.z * 0.5f, 0.f);
            v.w = fmaxf(v.w * 0.5f, 0.f);
        }
        float* p = s_acc + d * 128 + lane * 4;
        atomicAdd(p, v.x); atomicAdd(p + 1, v.y);
        atomicAdd(p + 2, v.z); atomicAdd(p + 3, v.w);
    }
    __syncthreads();
    for (int i = threadIdx.x * 4; i < NL * 128; i += blockDim.x * 4) {
        float4 v = *(float4*)(s_acc + i);
        red_add4(out + i, v.x, v.y, v.z, v.w);
    }
}

// ---------------- small label GEMM: out = A@W (+bias)(+base)(relu), *scale --
template <int KK, int NO, bool RELU>
__device__ __forceinline__
void label_gemm_body(const float* __restrict__ A,
                     const float* __restrict__ W,
                     const float* __restrict__ bias,
                     const float* __restrict__ base,
                     float* __restrict__ out, float scale, float* sm) {
    constexpr int TM = 4;
    constexpr int TN = NO / 16;
    float* sA = sm;
    float* sW = sm + NL * KK;
    int tid = threadIdx.x;
    int tx = tid & 15;
    int ty = tid >> 4;
    for (int i = tid; i < NL * KK / 4; i += 256) ((float4*)sA)[i] = ((const float4*)A)[i];
    for (int i = tid; i < KK * NO / 4; i += 256) ((float4*)sW)[i] = ((const float4*)W)[i];
    __syncthreads();
    float accv[TM][TN];
#pragma unroll
    for (int i = 0; i < TM; i++)
#pragma unroll
        for (int j = 0; j < TN; j++) accv[i][j] = 0.f;
#pragma unroll 8
    for (int k = 0; k < KK; k++) {
        float a[TM], b[TN];
#pragma unroll
        for (int i = 0; i < TM; i++) a[i] = sA[(ty * TM + i) * KK + k];
#pragma unroll
        for (int j = 0; j < TN; j += 4) {
            float4 bv = *(const float4*)(sW + k * NO + tx * TN + j);
            b[j] = bv.x; b[j + 1] = bv.y; b[j + 2] = bv.z; b[j + 3] = bv.w;
        }
#pragma unroll
        for (int i = 0; i < TM; i++)
#pragma unroll
            for (int j = 0; j < TN; j++) accv[i][j] = fmaf(a[i], b[j], accv[i][j]);
    }
#pragma unroll
    for (int i = 0; i < TM; i++) {
        int r = ty * TM + i;
#pragma unroll
        for (int j = 0; j < TN; j++) {
            int c = tx * TN + j;
            float v = accv[i][j];
            if (bias) v += bias[c];
            if (base) v += base[r * NO + c];
            if (RELU) v = fmaxf(v, 0.f);
            out[r * NO + c] = v * scale;
        }
    }
}

template <int KK, int NO, bool RELU>
__global__ void label_gemm_kernel(const float* __restrict__ A,
                                  const float* __restrict__ W,
                                  const float* __restrict__ bias,
                                  const float* __restrict__ base,
                                  float* __restrict__ out) {
    extern __shared__ float sm[];
    label_gemm_body<KK, NO, RELU>(A, W, bias, base, out, 1.0f, sm);
}

template <int KK, int NO>
__global__ void label_gemm_pair_kernel(const float* __restrict__ A,
                                       const float* __restrict__ W0, float scale0,
                                       float* __restrict__ out0,
                                       const float* __restrict__ W1,
                                       const float* __restrict__ bias1,
                                       float* __restrict__ out1) {
    extern __shared__ float sm[];
    if (blockIdx.x == 0)
        label_gemm_body<KK, NO, false>(A, W0, nullptr, nullptr, out0, scale0, sm);
    else
        label_gemm_body<KK, NO, false>(A, W1, bias1, nullptr, out1, 1.0f, sm);
}

// ---------------- host launcher --------------------------------------------
extern "C" void kernel_launch(void* const* d_in, const int* in_sizes, int n_in,
                              void* d_out, int out_size) {
    const float* x_paper = (const float*)d_in[0];
    const float* x_label = (const float*)d_in[1];
    const float* W1g  = (const float*)d_in[2];
    const float* b1g  = (const float*)d_in[3];
    const float* W1ri = (const float*)d_in[4];
    const float* W1oi = (const float*)d_in[5];
    const float* b1i  = (const float*)d_in[6];
    const float* W1rr = (const float*)d_in[7];
    const float* W1or = (const float*)d_in[8];
    const float* b1r  = (const float*)d_in[9];
    const float* W2g  = (const float*)d_in[10];
    const float* b2g  = (const float*)d_in[11];
    const float* W2ri = (const float*)d_in[12];
    const float* W2oi = (const float*)d_in[13];
    const float* b2i  = (const float*)d_in[14];
    const float* W2rr = (const float*)d_in[15];
    const float* W2or = (const float*)d_in[16];
    const float* b2r  = (const float*)d_in[17];
    const int* cites_src = (const int*)d_in[18];
    const int* cites_dst = (const int*)d_in[19];
    const int* is_src    = (const int*)d_in[20];
    const int* is_dst    = (const int*)d_in[21];
    const int* rev_src   = (const int*)d_in[22];
    const int* rev_dst   = (const int*)d_in[23];
    float* out = (float*)d_out;

    float *deg, *dis, *acc, *aggL1, *aggL2, *xlW1, *xllin1, *xl1, *xlW2, *xllin2;
    uint32_t* ys;
    cudaGetSymbolAddress((void**)&deg, g_deg);
    cudaGetSymbolAddress((void**)&dis, g_dis);
    cudaGetSymbolAddress((void**)&ys, g_ys);
    cudaGetSymbolAddress((void**)&acc, g_acc);
    cudaGetSymbolAddress((void**)&aggL1, g_aggL1);
    cudaGetSymbolAddress((void**)&aggL2, g_aggL2);
    cudaGetSymbolAddress((void**)&xlW1, g_xlW1);
    cudaGetSymbolAddress((void**)&xllin1, g_xllin1);
    cudaGetSymbolAddress((void**)&xl1, g_xl1);
    cudaGetSymbolAddress((void**)&xlW2, g_xlW2);
    cudaGetSymbolAddress((void**)&xllin2, g_xllin2);

    const int smem_g128 = (64 * 68 + 2 * 64 * 136 + 128) * 4;  // 87,552
    const int smem_g64  = (64 * 68 + 2 * 64 * 72 + 64) * 4;    // 54,528
    const int smem_lg_64_128  = (NL * 64 + 64 * 128) * 4;
    const int smem_lg_128_128 = (NL * 128 + 128 * 128) * 4;
    const int smem_lg_128_64  = (NL * 128 + 128 * 64) * 4;
    cudaFuncSetAttribute(gemm_dual_bf16<128, false, false>, cudaFuncAttributeMaxDynamicSharedMemorySize, smem_g128);
    cudaFuncSetAttribute(gemm_dual_bf16<64, true, true>,    cudaFuncAttributeMaxDynamicSharedMemorySize, smem_g64);
    cudaFuncSetAttribute(label_gemm_pair_kernel<64, 128>,  cudaFuncAttributeMaxDynamicSharedMemorySize, smem_lg_64_128);
    cudaFuncSetAttribute(label_gemm_pair_kernel<128, 64>,  cudaFuncAttributeMaxDynamicSharedMemorySize, smem_lg_128_64);
    cudaFuncSetAttribute(label_gemm_kernel<128, 128, true>, cudaFuncAttributeMaxDynamicSharedMemorySize, smem_lg_128_128);
    cudaFuncSetAttribute(label_gemm_kernel<128, 64, false>, cudaFuncAttributeMaxDynamicSharedMemorySize, smem_lg_128_64);

    // ---- degree / dis ----
    const int ZTOT = NP + NL * FP + NL * HD;
    zero_all_kernel<<<(ZTOT + 255) / 256, 256>>>(deg, aggL1, aggL2);
    deg_kernel<<<(EC / 4 + 255) / 256, 256>>>(cites_dst, deg, EC / 4);
    dis_kernel<<<(NP + 255) / 256, 256>>>(deg, dis, NP);

    // cites block counts: U=4 edges/group, LPE=F/8 lanes/group
    const int G = (EC + 3) / 4;                     // 400000 groups
    const int BC1 = (G * 16 + 255) / 256;           // F=128: 25000
    const int BC2 = (G * 8 + 255) / 256;            // F=64:  12500

    // ---- layer 1 ----
    label_gemm_pair_kernel<64, 128><<<2, 256, smem_lg_64_128>>>(
        x_label, W1rr, 1.0f, xlW1, W1oi, b1i, xllin1);
    gemm_dual_bf16<128, false, false><<<(NP + 63) / 64, 256, smem_g128>>>(
        x_paper, W1g, W1or, b1g, b1r, dis, ys, acc, NP);
    fused_edge_kernel<128, true, false><<<BC1 + 1024, 256>>>(
        ys, dis, cites_src, cites_dst,
        xlW1, rev_src, rev_dst,
        x_paper, is_src, is_dst, aggL1,
        acc, BC1);
    label_gemm_kernel<128, 128, true><<<1, 256, smem_lg_128_128>>>(aggL1, W1ri, nullptr, xllin1, xl1);

    // ---- layer 2 ----
    scatter_label_kernel<true><<<512, 256>>>(acc, is_src, is_dst, aggL2, EIS);
    label_gemm_pair_kernel<128, 64><<<2, 256, smem_lg_128_64>>>(
        xl1, W2rr, 0.5f, xlW2, W2oi, b2i, xllin2);
    gemm_dual_bf16<64, true, true><<<(NP + 63) / 64, 256, smem_g64>>>(
        acc, W2g, W2or, b2g, b2r, dis, ys, out, NP);
    fused_edge_kernel<64, false, false><<<BC2 + 512, 256>>>(
        ys, dis, cites_src, cites_dst,
        xlW2, rev_src, rev_dst,
        nullptr, nullptr, nullptr, nullptr,
        out, BC2);
    label_gemm_kernel<128, 64, false><<<1, 256, smem_lg_128_64>>>(aggL2, W2ri, nullptr, xllin2, out + (size_t)NP * ED);
}

// round 17
// speedup vs baseline: 1.2771x; 1.2771x over previous
#include <cuda_runtime.h>
#include <cuda_fp16.h>
#include <cstdint>

#define NP   100000
#define NL   64
#define FP   128
#define FL   64
#define HD   128
#define ED   64
#define EC   1600000
#define EIS  100000
#define EREV 100000

// ---------------- scratch (device globals; no allocation allowed) ----------
__device__ float g_deg[NP];
__device__ float g_dis[NP];
__device__ uint32_t g_ys[NP * HD / 2];  // half2-packed dis*y (layer1: 64 words/row; layer2: 32)
__device__ float g_acc[NP * HD];        // layer-1 accumulator (128 cols)
__device__ float g_aggL1[NL * FP];
__device__ float g_aggL2[NL * HD];
__device__ float g_xlW1[NL * HD];
__device__ float g_xllin1[NL * HD];
__device__ float g_xl1[NL * HD];
__device__ float g_xlW2[NL * ED];
__device__ float g_xllin2[NL * ED];

// ---------------- helpers ---------------------------------------------------
__device__ __forceinline__ void red_add4(float* p, float a, float b, float c, float d) {
    asm volatile("red.global.add.v4.f32 [%0], {%1,%2,%3,%4};"
                 :: "l"(p), "f"(a), "f"(b), "f"(c), "f"(d) : "memory");
}
__device__ __forceinline__ void red_add1(float* p, float v) {
    asm volatile("red.global.add.f32 [%0], %1;" :: "l"(p), "f"(v) : "memory");
}

// pack two f32 into bf16x2 word: lo half = first arg
__device__ __forceinline__ uint32_t pack_bf2(float lo, float hi) {
    uint32_t u;
    asm("cvt.rn.bf16x2.f32 %0, %1, %2;" : "=r"(u) : "f"(hi), "f"(lo));
    return u;
}

__device__ __forceinline__ void mma_bf16(float* d, const uint32_t* a, uint32_t b0, uint32_t b1) {
    asm("mma.sync.aligned.m16n8k16.row.col.f32.bf16.bf16.f32 "
        "{%0,%1,%2,%3},{%4,%5,%6,%7},{%8,%9},{%0,%1,%2,%3};"
        : "+f"(d[0]), "+f"(d[1]), "+f"(d[2]), "+f"(d[3])
        : "r"(a[0]), "r"(a[1]), "r"(a[2]), "r"(a[3]), "r"(b0), "r"(b1));
}

__device__ __forceinline__ uint32_t pack_h2(float lo, float hi) {
    __half2 h = __float22half2_rn(make_float2(lo, hi));
    return *(uint32_t*)&h;
}

// ---------------- setup kernels ---------------------------------------------
__global__ void zero_all_kernel(float* deg, float* aggL1, float* aggL2) {
    int i = blockIdx.x * blockDim.x + threadIdx.x;
    if (i < NP) deg[i] = 0.f;
    else if (i < NP + NL * FP) aggL1[i - NP] = 0.f;
    else if (i < NP + NL * FP + NL * HD) aggL2[i - NP - NL * FP] = 0.f;
}

__global__ void deg_kernel(const int* __restrict__ dst, float* __restrict__ deg, int E4) {
    int i = blockIdx.x * blockDim.x + threadIdx.x;
    if (i < E4) {
        int4 v = ((const int4*)dst)[i];
        red_add1(&deg[v.x], 1.f);
        red_add1(&deg[v.y], 1.f);
        red_add1(&deg[v.z], 1.f);
        red_add1(&deg[v.w], 1.f);
    }
}

__global__ void dis_kernel(const float* __restrict__ deg, float* __restrict__ dis, int n) {
    int i = blockIdx.x * blockDim.x + threadIdx.x;
    if (i < n) dis[i] = rsqrtf(deg[i] + 1.f);
}

// ---------------- big dual GEMM via BF16 m16n8k16 mma.sync -------------------
// ys(half2) = OS * dis * (X @ Wa)
// acc(f32)  = OS * (X @ Wb + ba + bb + dis^2 * (X @ Wa))
// X/W converted to bf16x2 words in smem (packed along K). Full K=128 resident.
// CTA tile 64 x BN, 256 threads = 2(M) x 4(N) warps; warp tile 32 x BN/4.
template <int BN, bool PRE, bool HALF_OUT>
__global__ __launch_bounds__(256, 2)
void gemm_dual_bf16(const float* __restrict__ X,
                    const float* __restrict__ Wa,
                    const float* __restrict__ Wb,
                    const float* __restrict__ ba,
                    const float* __restrict__ bb,
                    const float* __restrict__ dis,
                    uint32_t* __restrict__ ys,
                    float* __restrict__ acc,
                    int M) {
    constexpr int K = 128;
    constexpr int KW = K / 2;         // 64 words along K
    constexpr int LDX = KW + 4;       // 68
    constexpr int LDW = BN + 8;       // 136 / 72
    constexpr int NAW = (BN / 4) / 8; // 4 (BN=128) / 2 (BN=64)
    constexpr float OS = HALF_OUT ? 0.5f : 1.0f;

    extern __shared__ uint32_t smu[];
    uint32_t* Xs = smu;                     // 64 * LDX
    uint32_t* Was = Xs + 64 * LDX;          // KW * LDW
    uint32_t* Wbs = Was + KW * LDW;         // KW * LDW
    float* bsum = (float*)(Wbs + KW * LDW); // BN

    const int tid = threadIdx.x;
    const int lane = tid & 31;
    const int wid = tid >> 5;
    const int wm = wid & 1;
    const int wn = wid >> 1;
    const int r = lane >> 2;
    const int c = lane & 3;
    const int row0 = blockIdx.x * 64;

    if (tid < BN) bsum[tid] = ba[tid] + bb[tid];

    // X tile: 64 rows x 128 cols -> bf16x2 words [row][kw]
    for (int idx = tid; idx < 64 * 32; idx += 256) {
        int rr = idx >> 5, c4 = idx & 31;
        float4 v = make_float4(0.f, 0.f, 0.f, 0.f);
        if (row0 + rr < M) {
            v = *(const float4*)(X + (size_t)(row0 + rr) * K + c4 * 4);
            if (PRE) {
                v.x = fmaxf(v.x * 0.5f, 0.f);
                v.y = fmaxf(v.y * 0.5f, 0.f);
                v.z = fmaxf(v.z * 0.5f, 0.f);
                v.w = fmaxf(v.w * 0.5f, 0.f);
            }
        }
        uint32_t* p = Xs + rr * LDX + c4 * 2;
        p[0] = pack_bf2(v.x, v.y);
        p[1] = pack_bf2(v.z, v.w);
    }
    // W tiles: words [kw][n] = pack(W[2kw][n], W[2kw+1][n])
    for (int idx = tid; idx < KW * (BN / 4); idx += 256) {
        int kw = idx / (BN / 4), cc = idx % (BN / 4);
        const float4 a0 = ((const float4*)(Wa + (size_t)(2 * kw) * BN))[cc];
        const float4 a1 = ((const float4*)(Wa + (size_t)(2 * kw + 1) * BN))[cc];
        const float4 b0 = ((const float4*)(Wb + (size_t)(2 * kw) * BN))[cc];
        const float4 b1 = ((const float4*)(Wb + (size_t)(2 * kw + 1) * BN))[cc];
        uint32_t* pa = Was + kw * LDW + cc * 4;
        uint32_t* pb = Wbs + kw * LDW + cc * 4;
        pa[0] = pack_bf2(a0.x, a1.x); pa[1] = pack_bf2(a0.y, a1.y);
        pa[2] = pack_bf2(a0.z, a1.z); pa[3] = pack_bf2(a0.w, a1.w);
        pb[0] = pack_bf2(b0.x, b1.x); pb[1] = pack_bf2(b0.y, b1.y);
        pb[2] = pack_bf2(b0.z, b1.z); pb[3] = pack_bf2(b0.w, b1.w);
    }
    __syncthreads();

    float accY[2][NAW][4];
    float accL[2][NAW][4];
#pragma unroll
    for (int i = 0; i < 2; i++)
#pragma unroll
        for (int j = 0; j < NAW; j++)
#pragma unroll
            for (int q = 0; q < 4; q++) { accY[i][j][q] = 0.f; accL[i][j][q] = 0.f; }

#pragma unroll
    for (int ks = 0; ks < 8; ks++) {
        int k0 = ks * 8;   // word offset
        uint32_t a[2][4];
#pragma unroll
        for (int i = 0; i < 2; i++) {
            int base = wm * 32 + i * 16;
            a[i][0] = Xs[(base + r) * LDX + k0 + c];
            a[i][1] = Xs[(base + r + 8) * LDX + k0 + c];
            a[i][2] = Xs[(base + r) * LDX + k0 + c + 4];
            a[i][3] = Xs[(base + r + 8) * LDX + k0 + c + 4];
        }
#pragma unroll
        for (int j = 0; j < NAW; j++) {
            int n = wn * (BN / 4) + j * 8 + r;
            uint32_t b0 = Was[(k0 + c) * LDW + n];
            uint32_t b1 = Was[(k0 + c + 4) * LDW + n];
            mma_bf16(accY[0][j], a[0], b0, b1);
            mma_bf16(accY[1][j], a[1], b0, b1);
            uint32_t b2 = Wbs[(k0 + c) * LDW + n];
            uint32_t b3 = Wbs[(k0 + c + 4) * LDW + n];
            mma_bf16(accL[0][j], a[0], b2, b3);
            mma_bf16(accL[1][j], a[1], b2, b3);
        }
    }

    // epilogue
#pragma unroll
    for (int i = 0; i < 2; i++) {
        int row_lo = row0 + wm * 32 + i * 16 + r;
        int row_hi = row_lo + 8;
        float dlo = (row_lo < M) ? dis[row_lo] : 0.f;
        float dhi = (row_hi < M) ? dis[row_hi] : 0.f;
#pragma unroll
        for (int j = 0; j < NAW; j++) {
            int cb = wn * (BN / 4) + j * 8 + c * 2;
            float bs0 = bsum[cb], bs1 = bsum[cb + 1];
            if (row_lo < M) {
                float y0 = accY[i][j][0], y1 = accY[i][j][1];
                float l0 = accL[i][j][0], l1 = accL[i][j][1];
                ys[(size_t)row_lo * (BN / 2) + (cb >> 1)] =
                    pack_h2(OS * dlo * y0, OS * dlo * y1);
                float2 ao = make_float2(OS * (l0 + bs0 + dlo * dlo * y0),
                                        OS * (l1 + bs1 + dlo * dlo * y1));
                *(float2*)(acc + (size_t)row_lo * BN + cb) = ao;
            }
            if (row_hi < M) {
                float y0 = accY[i][j][2], y1 = accY[i][j][3];
                float l0 = accL[i][j][2], l1 = accL[i][j][3];
                ys[(size_t)row_hi * (BN / 2) + (cb >> 1)] =
                    pack_h2(OS * dhi * y0, OS * dhi * y1);
                float2 ao = make_float2(OS * (l0 + bs0 + dhi * dhi * y0),
                                        OS * (l1 + bs1 + dhi * dhi * y1));
                *(float2*)(acc + (size_t)row_hi * BN + cb) = ao;
            }
        }
    }
}

// ---------------- cites scatter (4-edge unrolled): acc[dst] += dis[dst]*ys[src]
// Each LPE-thread group handles U=4 consecutive edges with independent load
// chains in flight, then fires 4 no-return red.add.v4 stores.
template <int F>
__global__ __launch_bounds__(256)
void scatter_cites_kernel(const uint32_t* __restrict__ ys,
                          const float* __restrict__ dis,
                          const int* __restrict__ src,
                          const int* __restrict__ dst,
                          float* __restrict__ acc, int E) {
    constexpr int LPE = F / 4;    // lanes per edge: 32 (F=128) or 16 (F=64)
    constexpr int U = 4;
    int gid = (blockIdx.x * 256 + threadIdx.x) / LPE;
    int l = threadIdx.x & (LPE - 1);
    int e0 = gid * U;
    if (e0 >= E) return;

    int s[U], d[U];
    bool v[U];
#pragma unroll
    for (int u = 0; u < U; u++) {
        v[u] = (e0 + u) < E;
        int e = v[u] ? (e0 + u) : e0;
        s[u] = __ldg(src + e);
        d[u] = __ldg(dst + e);
    }
    float dd[U];
#pragma unroll
    for (int u = 0; u < U; u++) dd[u] = __ldg(dis + d[u]);
    uint2 wv[U];
#pragma unroll
    for (int u = 0; u < U; u++)
        wv[u] = *(const uint2*)(ys + (size_t)s[u] * (F / 2) + l * 2);
#pragma unroll
    for (int u = 0; u < U; u++) {
        if (!v[u]) continue;
        float2 p0 = __half22float2(*(__half2*)&wv[u].x);
        float2 p1 = __half22float2(*(__half2*)&wv[u].y);
        float* p = acc + (size_t)d[u] * F + l * 4;
        red_add4(p, p0.x * dd[u], p0.y * dd[u], p1.x * dd[u], p1.y * dd[u]);
    }
}

// ---------------- rev scatter: acc[dst] += tab[src], tab is 64 rows ---------
template <int F>
__global__ void scatter_rev_kernel(const float* __restrict__ tab,
                                   const int* __restrict__ src,
                                   const int* __restrict__ dst,
                                   float* __restrict__ acc, int E) {
    constexpr int LPE = F / 4;
    __shared__ float s_tab[NL * F];
    for (int i = threadIdx.x; i < NL * F; i += blockDim.x) s_tab[i] = tab[i];
    __syncthreads();
    int ge = (blockIdx.x * blockDim.x + threadIdx.x) / LPE;
    int l = threadIdx.x & (LPE - 1);
    int ne = (gridDim.x * blockDim.x) / LPE;
    for (int e = ge; e < E; e += ne) {
        int s = __ldg(src + e);
        int d = __ldg(dst + e);
        float4 v = *(const float4*)(s_tab + s * F + l * 4);
        float* p = acc + (size_t)d * F + l * 4;
        red_add4(p, v.x, v.y, v.z, v.w);
    }
}

// ---------------- label scatter (privatized): out[64,128] += X[src] ---------
template <bool PRE>
__global__ void scatter_label_kernel(const float* __restrict__ X,
                                     const int* __restrict__ src,
                                     const int* __restrict__ dst,
                                     float* __restrict__ out, int E) {
    __shared__ float s_acc[NL * 128];
    for (int i = threadIdx.x; i < NL * 128; i += blockDim.x) s_acc[i] = 0.f;
    __syncthreads();
    int warp_in = threadIdx.x >> 5;
    int lane = threadIdx.x & 31;
    int gw = blockIdx.x * (blockDim.x >> 5) + warp_in;
    int nw = gridDim.x * (blockDim.x >> 5);
    for (int e = gw; e < E; e += nw) {
        int s = __ldg(src + e);
        int d = __ldg(dst + e);
        float4 v = *(const float4*)(X + (size_t)s * 128 + lane * 4);
        if (PRE) {
            v.x = fmaxf(v.x * 0.5f, 0.f);
            v.y = fmaxf(v.y * 0.5f, 0.f);
            v.z = fmaxf(v.z * 0.5f, 0.f);
            v.w = fmaxf(v.w * 0.5f, 0.f);
        }
        float* p = s_acc + d * 128 + lane * 4;
        atomicAdd(p, v.x); atomicAdd(p + 1, v.y);
        atomicAdd(p + 2, v.z); atomicAdd(p + 3, v.w);
    }
    __syncthreads();
    for (int i = threadIdx.x * 4; i < NL * 128; i += blockDim.x * 4) {
        float4 v = *(float4*)(s_acc + i);
        red_add4(out + i, v.x, v.y, v.z, v.w);
    }
}

// ---------------- small label GEMM: out = A@W (+bias)(+base)(relu), *scale --
template <int KK, int NO, bool RELU>
__device__ __forceinline__
void label_gemm_body(const float* __restrict__ A,
                     const float* __restrict__ W,
                     const float* __restrict__ bias,
                     const float* __restrict__ base,
                     float* __restrict__ out, float scale, float* sm) {
    constexpr int TM = 4;
    constexpr int TN = NO / 16;
    float* sA = sm;
    float* sW = sm + NL * KK;
    int tid = threadIdx.x;
    int tx = tid & 15;
    int ty = tid >> 4;
    for (int i = tid; i < NL * KK / 4; i += 256) ((float4*)sA)[i] = ((const float4*)A)[i];
    for (int i = tid; i < KK * NO / 4; i += 256) ((float4*)sW)[i] = ((const float4*)W)[i];
    __syncthreads();
    float accv[TM][TN];
#pragma unroll
    for (int i = 0; i < TM; i++)
#pragma unroll
        for (int j = 0; j < TN; j++) accv[i][j] = 0.f;
#pragma unroll 8
    for (int k = 0; k < KK; k++) {
        float a[TM], b[TN];
#pragma unroll
        for (int i = 0; i < TM; i++) a[i] = sA[(ty * TM + i) * KK + k];
#pragma unroll
        for (int j = 0; j < TN; j += 4) {
            float4 bv = *(const float4*)(sW + k * NO + tx * TN + j);
            b[j] = bv.x; b[j + 1] = bv.y; b[j + 2] = bv.z; b[j + 3] = bv.w;
        }
#pragma unroll
        for (int i = 0; i < TM; i++)
#pragma unroll
            for (int j = 0; j < TN; j++) accv[i][j] = fmaf(a[i], b[j], accv[i][j]);
    }
#pragma unroll
    for (int i = 0; i < TM; i++) {
        int r = ty * TM + i;
#pragma unroll
        for (int j = 0; j < TN; j++) {
            int c = tx * TN + j;
            float v = accv[i][j];
            if (bias) v += bias[c];
            if (base) v += base[r * NO + c];
            if (RELU) v = fmaxf(v, 0.f);
            out[r * NO + c] = v * scale;
        }
    }
}

template <int KK, int NO, bool RELU>
__global__ void label_gemm_kernel(const float* __restrict__ A,
                                  const float* __restrict__ W,
                                  const float* __restrict__ bias,
                                  const float* __restrict__ base,
                                  float* __restrict__ out) {
    extern __shared__ float sm[];
    label_gemm_body<KK, NO, RELU>(A, W, bias, base, out, 1.0f, sm);
}

template <int KK, int NO>
__global__ void label_gemm_pair_kernel(const float* __restrict__ A,
                                       const float* __restrict__ W0, float scale0,
                                       float* __restrict__ out0,
                                       const float* __restrict__ W1,
                                       const float* __restrict__ bias1,
                                       float* __restrict__ out1) {
    extern __shared__ float sm[];
    if (blockIdx.x == 0)
        label_gemm_body<KK, NO, false>(A, W0, nullptr, nullptr, out0, scale0, sm);
    else
        label_gemm_body<KK, NO, false>(A, W1, bias1, nullptr, out1, 1.0f, sm);
}

// ---------------- host launcher --------------------------------------------
extern "C" void kernel_launch(void* const* d_in, const int* in_sizes, int n_in,
                              void* d_out, int out_size) {
    const float* x_paper = (const float*)d_in[0];
    const float* x_label = (const float*)d_in[1];
    const float* W1g  = (const float*)d_in[2];
    const float* b1g  = (const float*)d_in[3];
    const float* W1ri = (const float*)d_in[4];
    const float* W1oi = (const float*)d_in[5];
    const float* b1i  = (const float*)d_in[6];
    const float* W1rr = (const float*)d_in[7];
    const float* W1or = (const float*)d_in[8];
    const float* b1r  = (const float*)d_in[9];
    const float* W2g  = (const float*)d_in[10];
    const float* b2g  = (const float*)d_in[11];
    const float* W2ri = (const float*)d_in[12];
    const float* W2oi = (const float*)d_in[13];
    const float* b2i  = (const float*)d_in[14];
    const float* W2rr = (const float*)d_in[15];
    const float* W2or = (const float*)d_in[16];
    const float* b2r  = (const float*)d_in[17];
    const int* cites_src = (const int*)d_in[18];
    const int* cites_dst = (const int*)d_in[19];
    const int* is_src    = (const int*)d_in[20];
    const int* is_dst    = (const int*)d_in[21];
    const int* rev_src   = (const int*)d_in[22];
    const int* rev_dst   = (const int*)d_in[23];
    float* out = (float*)d_out;

    float *deg, *dis, *acc, *aggL1, *aggL2, *xlW1, *xllin1, *xl1, *xlW2, *xllin2;
    uint32_t* ys;
    cudaGetSymbolAddress((void**)&deg, g_deg);
    cudaGetSymbolAddress((void**)&dis, g_dis);
    cudaGetSymbolAddress((void**)&ys, g_ys);
    cudaGetSymbolAddress((void**)&acc, g_acc);
    cudaGetSymbolAddress((void**)&aggL1, g_aggL1);
    cudaGetSymbolAddress((void**)&aggL2, g_aggL2);
    cudaGetSymbolAddress((void**)&xlW1, g_xlW1);
    cudaGetSymbolAddress((void**)&xllin1, g_xllin1);
    cudaGetSymbolAddress((void**)&xl1, g_xl1);
    cudaGetSymbolAddress((void**)&xlW2, g_xlW2);
    cudaGetSymbolAddress((void**)&xllin2, g_xllin2);

    const int smem_g128 = (64 * 68 + 2 * 64 * 136 + 128) * 4;  // 87,552
    const int smem_g64  = (64 * 68 + 2 * 64 * 72 + 64) * 4;    // 54,528
    const int smem_lg_64_128  = (NL * 64 + 64 * 128) * 4;
    const int smem_lg_128_128 = (NL * 128 + 128 * 128) * 4;
    const int smem_lg_128_64  = (NL * 128 + 128 * 64) * 4;
    cudaFuncSetAttribute(gemm_dual_bf16<128, false, false>, cudaFuncAttributeMaxDynamicSharedMemorySize, smem_g128);
    cudaFuncSetAttribute(gemm_dual_bf16<64, true, true>,    cudaFuncAttributeMaxDynamicSharedMemorySize, smem_g64);
    cudaFuncSetAttribute(label_gemm_pair_kernel<64, 128>,  cudaFuncAttributeMaxDynamicSharedMemorySize, smem_lg_64_128);
    cudaFuncSetAttribute(label_gemm_pair_kernel<128, 64>,  cudaFuncAttributeMaxDynamicSharedMemorySize, smem_lg_128_64);
    cudaFuncSetAttribute(label_gemm_kernel<128, 128, true>, cudaFuncAttributeMaxDynamicSharedMemorySize, smem_lg_128_128);
    cudaFuncSetAttribute(label_gemm_kernel<128, 64, false>, cudaFuncAttributeMaxDynamicSharedMemorySize, smem_lg_128_64);

    // ---- degree / dis ----
    const int ZTOT = NP + NL * FP + NL * HD;
    zero_all_kernel<<<(ZTOT + 255) / 256, 256>>>(deg, aggL1, aggL2);
    deg_kernel<<<(EC / 4 + 255) / 256, 256>>>(cites_dst, deg, EC / 4);
    dis_kernel<<<(NP + 255) / 256, 256>>>(deg, dis, NP);

    // grid sizes for 4-edge-unrolled cites scatters
    const int G = (EC + 3) / 4;                       // edge groups
    const int blocks128 = (G * 32 + 255) / 256;       // LPE=32
    const int blocks64  = (G * 16 + 255) / 256;       // LPE=16

    // ---- layer 1 ----
    gemm_dual_bf16<128, false, false><<<(NP + 63) / 64, 256, smem_g128>>>(
        x_paper, W1g, W1or, b1g, b1r, dis, ys, acc, NP);
    label_gemm_pair_kernel<64, 128><<<2, 256, smem_lg_64_128>>>(
        x_label, W1rr, 1.0f, xlW1, W1oi, b1i, xllin1);
    scatter_cites_kernel<128><<<blocks128, 256>>>(ys, dis, cites_src, cites_dst, acc, EC);
    scatter_rev_kernel<128><<<512, 256>>>(xlW1, rev_src, rev_dst, acc, EREV);
    scatter_label_kernel<false><<<512, 256>>>(x_paper, is_src, is_dst, aggL1, EIS);
    label_gemm_kernel<128, 128, true><<<1, 256, smem_lg_128_128>>>(aggL1, W1ri, nullptr, xllin1, xl1);

    // ---- layer 2 ----
    scatter_label_kernel<true><<<512, 256>>>(acc, is_src, is_dst, aggL2, EIS);
    gemm_dual_bf16<64, true, true><<<(NP + 63) / 64, 256, smem_g64>>>(
        acc, W2g, W2or, b2g, b2r, dis, ys, out, NP);
    label_gemm_pair_kernel<128, 64><<<2, 256, smem_lg_128_64>>>(
        xl1, W2rr, 0.5f, xlW2, W2oi, b2i, xllin2);
    scatter_cites_kernel<64><<<blocks64, 256>>>(ys, dis, cites_src, cites_dst, out, EC);
    scatter_rev_kernel<64><<<512, 256>>>(xlW2, rev_src, rev_dst, out, EREV);
    label_gemm_kernel<128, 64, false><<<1, 256, smem_lg_128_64>>>(aggL2, W2ri, nullptr, xllin2, out + (size_t)NP * ED);
}